// round 7
// baseline (speedup 1.0000x reference)
#include <cuda_runtime.h>

// Shapes fixed by the dataset:
// log_belief: (N=4, Cin=4, H=128, W=128)  f32
// log_kernel: (N=4, Cin=4, 100, H, W)     f32   (100 = Cout*K*K = 4*25)
// out:        (N=4, Cout=4, H, W)         f32
#define HW     16384
#define CSHIFT 12.0f

// Scatter-form kernel: every load is an aligned LDG.128 of the lane's own quad.
// Term exp(lb[xi] + lk[tap][xi]) contributes to output x = xi + kx - 2, i.e.
// lane-local accumulator A[o + kx]  (o = xi & 3), covering outputs 4t-2..4t+5.
// Cross-lane spill (A0,A1 -> lane t+1; A6,A7 -> lane t-1... see end) resolved
// with 4 shuffles once at the end. Out-of-range outputs are discarded there.
//
// Block (128 thr = 4 warps) = (n, co, yo pair). Warp j: row r=j>>1, ci-group
// cig=j&1 (2 channels). Exp-sums additive across ci -> smem combine.
__global__ __launch_bounds__(128, 10)
void propagate_lse_v7(const float* __restrict__ lb_g,
                      const float* __restrict__ lk_g,
                      float* __restrict__ out)
{
    __shared__ float part[4][128];

    int bid = blockIdx.x;          // 0..1023 = (n, co, yo2)
    int n   = bid >> 8;
    int co  = (bid >> 6) & 3;
    int yo2 = bid & 63;

    int j   = threadIdx.x >> 5;    // warp in block
    int t   = threadIdx.x & 31;    // lane: inputs/outputs xo = 4t..4t+3
    int r   = j >> 1;
    int cig = j & 1;
    int yo  = yo2 * 2 + r;

    float A[8];
    #pragma unroll
    for (int k = 0; k < 8; k++) A[k] = 0.0f;

    // valid ky range is contiguous: 0 <= yi = yo+2-ky < 128
    int ky_lo = yo > 125 ? yo - 125 : 0;
    int ky_hi = yo < 2 ? yo + 2 : 4;

    #pragma unroll 1
    for (int ky = ky_lo; ky <= ky_hi; ky++) {
        int yi = yo + 2 - ky;

        #pragma unroll 1
        for (int cc = 0; cc < 2; cc++) {
            int ci = cig * 2 + cc;

            const float4* b4 = (const float4*)(lb_g + (size_t)((n*4 + ci)*128 + yi) * 128);
            float4 b = __ldg(b4 + t);

            const float* plane0 = lk_g
                + (size_t)((n*4 + ci)*100 + co*25 + ky*5) * HW
                + (size_t)yi * 128;

            // batch the 5 aligned tap loads, then 20 exps into A[o+kx]
            float4 q0 = __ldcs((const float4*)(plane0 + 0*HW) + t);
            float4 q1 = __ldcs((const float4*)(plane0 + 1*HW) + t);
            float4 q2 = __ldcs((const float4*)(plane0 + 2*HW) + t);
            float4 q3 = __ldcs((const float4*)(plane0 + 3*HW) + t);
            float4 q4 = __ldcs((const float4*)(plane0 + 4*HW) + t);

            A[0] += __expf(b.x + q0.x + CSHIFT);
            A[1] += __expf(b.y + q0.y + CSHIFT);
            A[2] += __expf(b.z + q0.z + CSHIFT);
            A[3] += __expf(b.w + q0.w + CSHIFT);

            A[1] += __expf(b.x + q1.x + CSHIFT);
            A[2] += __expf(b.y + q1.y + CSHIFT);
            A[3] += __expf(b.z + q1.z + CSHIFT);
            A[4] += __expf(b.w + q1.w + CSHIFT);

            A[2] += __expf(b.x + q2.x + CSHIFT);
            A[3] += __expf(b.y + q2.y + CSHIFT);
            A[4] += __expf(b.z + q2.z + CSHIFT);
            A[5] += __expf(b.w + q2.w + CSHIFT);

            A[3] += __expf(b.x + q3.x + CSHIFT);
            A[4] += __expf(b.y + q3.y + CSHIFT);
            A[5] += __expf(b.z + q3.z + CSHIFT);
            A[6] += __expf(b.w + q3.w + CSHIFT);

            A[4] += __expf(b.x + q4.x + CSHIFT);
            A[5] += __expf(b.y + q4.y + CSHIFT);
            A[6] += __expf(b.z + q4.z + CSHIFT);
            A[7] += __expf(b.w + q4.w + CSHIFT);
        }
    }

    // A[k] targets output x = 4t + (k-2).
    // k=2..5 are this lane's outputs j=0..3; k=6,7 go to lane t+1 (its j=0,1);
    // k=0,1 go to lane t-1 (its j=2,3). Invalid at the grid edge -> zero.
    unsigned FULL = 0xFFFFFFFFu;
    float up6 = __shfl_up_sync(FULL, A[6], 1);    // from lane t-1
    float up7 = __shfl_up_sync(FULL, A[7], 1);
    float dn0 = __shfl_down_sync(FULL, A[0], 1);  // from lane t+1
    float dn1 = __shfl_down_sync(FULL, A[1], 1);
    if (t == 0)  { up6 = 0.f; up7 = 0.f; }
    if (t == 31) { dn0 = 0.f; dn1 = 0.f; }

    float4 sv;
    sv.x = A[2] + up6;
    sv.y = A[3] + up7;
    sv.z = A[4] + dn0;
    sv.w = A[5] + dn1;
    ((float4*)part[j])[t] = sv;
    __syncthreads();

    // combine ci-groups and write: 256 outputs, 128 threads -> 2 each
    int i = threadIdx.x;
    #pragma unroll
    for (int rr = 0; rr < 2; rr++) {
        float sum = part[rr*2 + 0][i] + part[rr*2 + 1][i];
        out[(size_t)((n*4 + co)*128 + yo2*2 + rr) * 128 + i] = __logf(sum) - CSHIFT;
    }
}

extern "C" void kernel_launch(void* const* d_in, const int* in_sizes, int n_in,
                              void* d_out, int out_size)
{
    const float* lb = (const float*)d_in[0];
    const float* lk = (const float*)d_in[1];
    float* out = (float*)d_out;
    // 1024 blocks: (n, co, yo/2)
    propagate_lse_v7<<<1024, 128>>>(lb, lk, out);
}